// round 5
// baseline (speedup 1.0000x reference)
#include <cuda_runtime.h>
#include <cuda_fp16.h>
#include <cstdint>

// Problem constants
#define Bn      8
#define Cn      128
#define HWn     262144          // 512*512
#define SCALESn 4
#define NSEGn   1024
#define EMBEDn  192
#define TOKROWS 1025
#define TOK_SIZE   (Bn*TOKROWS*EMBEDn)       // 1,574,400 per scale
#define SEG_TOTAL  (Bn*SCALESn*HWn)          // 8,388,608
#define SEG_OUT_OFF ((size_t)SCALESn*TOK_SIZE) // 6,297,600

// ---------------- scratch (static device globals; no runtime alloc) ----------
__device__ __half g_xt[(size_t)Bn*HWn*Cn];     // 0.5 GB: x transposed [b][pixel][c], fp16
__device__ int    g_sorted[SEG_TOTAL];         // sorted pixel ids per (b,scale)
__device__ int    g_cnt[Bn*SCALESn*NSEGn];     // per-segment counts
__device__ int    g_off[Bn*SCALESn*NSEGn];     // exclusive offsets
__device__ int    g_cursor[Bn*SCALESn*NSEGn];  // scatter cursors
__device__ float  g_sums[(size_t)SCALESn*Bn*NSEGn*Cn]; // [s][b][n][c]

// ---------------- K0: zero counts ----------------
__global__ void k_zero()
{
    int i = blockIdx.x * 1024 + threadIdx.x;
    if (i < Bn*SCALESn*NSEGn) g_cnt[i] = 0;
}

// ---------------- K1: transpose x [b][c][p] -> g_xt [b][p][c] (fp32 -> fp16) --
// tile: 64 pixels x 128 channels per block
__global__ void k_transpose(const float* __restrict__ x)
{
    __shared__ float sm[64 * 129];
    int b  = blockIdx.y;
    int p0 = blockIdx.x * 64;
    const float* xb = x + (size_t)b * Cn * HWn;
    int t = threadIdx.x;

#pragma unroll
    for (int it = 0; it < 32; ++it) {
        int i  = it * 256 + t;
        int c  = i >> 6;
        int px = i & 63;
        sm[px * 129 + c] = xb[(size_t)c * HWn + p0 + px];
    }
    __syncthreads();
    // write 1024 x 16B groups (8 halves each)
#pragma unroll
    for (int it = 0; it < 4; ++it) {
        int i  = it * 256 + t;
        int px = i >> 4;          // 0..63
        int g  = i & 15;          // 16-byte group within 256B row
        const float* s = &sm[px * 129 + g * 8];
        __half2 h0 = __floats2half2_rn(s[0], s[1]);
        __half2 h1 = __floats2half2_rn(s[2], s[3]);
        __half2 h2 = __floats2half2_rn(s[4], s[5]);
        __half2 h3 = __floats2half2_rn(s[6], s[7]);
        uint4 v;
        v.x = *reinterpret_cast<uint32_t*>(&h0);
        v.y = *reinterpret_cast<uint32_t*>(&h1);
        v.z = *reinterpret_cast<uint32_t*>(&h2);
        v.w = *reinterpret_cast<uint32_t*>(&h3);
        *reinterpret_cast<uint4*>(&g_xt[((size_t)b * HWn + p0 + px) * Cn + g * 8]) = v;
    }
}

// ---------------- K2: histogram (privatized in shared) ----------------
__global__ void k_hist(const int* __restrict__ seg)
{
    __shared__ int h[NSEGn];
    int bs = blockIdx.x >> 3;
    int chunk = blockIdx.x & 7;
    int t = threadIdx.x;
    for (int i = t; i < NSEGn; i += 256) h[i] = 0;
    __syncthreads();
    const int4* s4 = reinterpret_cast<const int4*>(seg + (size_t)bs * HWn + (size_t)chunk * 32768);
#pragma unroll 4
    for (int it = 0; it < 32; ++it) {
        int4 v = s4[it * 256 + t];
        atomicAdd(&h[v.x], 1);
        atomicAdd(&h[v.y], 1);
        atomicAdd(&h[v.z], 1);
        atomicAdd(&h[v.w], 1);
    }
    __syncthreads();
    for (int i = t; i < NSEGn; i += 256) atomicAdd(&g_cnt[bs * NSEGn + i], h[i]);
}

// ---------------- K3: exclusive scan of 1024 counts per (b,scale) ----------------
__global__ void k_scan()
{
    int bs = blockIdx.x;
    int t = threadIdx.x;
    int lane = t & 31, wid = t >> 5;
    int v = g_cnt[bs * NSEGn + t];
    int x = v;
#pragma unroll
    for (int d = 1; d < 32; d <<= 1) {
        int y = __shfl_up_sync(0xffffffffu, x, d);
        if (lane >= d) x += y;
    }
    __shared__ int ws[32];
    if (lane == 31) ws[wid] = x;
    __syncthreads();
    if (wid == 0) {
        int s = ws[lane];
#pragma unroll
        for (int d = 1; d < 32; d <<= 1) {
            int y = __shfl_up_sync(0xffffffffu, s, d);
            if (lane >= d) s += y;
        }
        ws[lane] = s;
    }
    __syncthreads();
    int excl = x - v + (wid ? ws[wid - 1] : 0);
    g_off[bs * NSEGn + t]    = excl;
    g_cursor[bs * NSEGn + t] = excl;
}

// ---------------- K4: scatter pixel ids into per-segment lists + seg cast-out ---
__global__ void k_scatter(const int* __restrict__ seg, float* __restrict__ segout)
{
    int bs = blockIdx.x >> 3;
    int chunk = blockIdx.x & 7;
    int t = threadIdx.x;
    const int4* s4 = reinterpret_cast<const int4*>(seg + (size_t)bs * HWn + (size_t)chunk * 32768);
    float4* o4 = reinterpret_cast<float4*>(segout + (size_t)bs * HWn + (size_t)chunk * 32768);
    int* cur = &g_cursor[bs * NSEGn];
    int* dst = &g_sorted[(size_t)bs * HWn];
#pragma unroll 2
    for (int it = 0; it < 32; ++it) {
        int i4 = it * 256 + t;
        int4 v = s4[i4];
        int px = chunk * 32768 + i4 * 4;
        int p;
        p = atomicAdd(cur + v.x, 1); dst[p] = px + 0;
        p = atomicAdd(cur + v.y, 1); dst[p] = px + 1;
        p = atomicAdd(cur + v.z, 1); dst[p] = px + 2;
        p = atomicAdd(cur + v.w, 1); dst[p] = px + 3;
        o4[i4] = make_float4((float)v.x, (float)v.y, (float)v.z, (float)v.w);
    }
}

// ---------------- K5: segment-sum via sorted gather (no atomics, fp16 rows) ------
// One launch per image b (grid 256): entire working set = xt[b] (64MB) fits L2,
// so scales 1..3 of each image re-read from L2 instead of DRAM.
// Block bx: s = bx>>6, g = bx&63. Warp w handles segs g*16+w*2+{0,1}.
// Lane owns 4 channels (8B per pixel row); warp reads one coalesced 256B row/pixel.
__global__ void k_reduce(int b)
{
    int bx = blockIdx.x;
    int s = bx >> 6;
    int g = bx & 63;
    int bs = b * SCALESn + s;
    int w = threadIdx.x >> 5, lane = threadIdx.x & 31;
    const __half* xb = g_xt + (size_t)b * HWn * Cn;

    for (int k = 0; k < 2; ++k) {
        int sg  = g * 16 + w * 2 + k;
        int off = g_off[bs * NSEGn + sg];
        int cnt = g_cnt[bs * NSEGn + sg];
        const int* list = g_sorted + (size_t)bs * HWn + off;

        float ax = 0.f, ay = 0.f, az = 0.f, aw = 0.f;
        int i0 = 0;
        for (; i0 + 32 <= cnt; i0 += 32) {
            int pl = list[i0 + lane];
#pragma unroll 16
            for (int j = 0; j < 32; ++j) {
                int p = __shfl_sync(0xffffffffu, pl, j);
                uint2 raw = *reinterpret_cast<const uint2*>(xb + (size_t)p * Cn + lane * 4);
                __half2 h0 = *reinterpret_cast<__half2*>(&raw.x);
                __half2 h1 = *reinterpret_cast<__half2*>(&raw.y);
                float2 f0 = __half22float2(h0);
                float2 f1 = __half22float2(h1);
                ax += f0.x; ay += f0.y; az += f1.x; aw += f1.y;
            }
        }
        if (i0 < cnt) {
            int idx = i0 + lane;
            int pl = (idx < cnt) ? list[idx] : 0;
            int m = cnt - i0;
            for (int j = 0; j < m; ++j) {
                int p = __shfl_sync(0xffffffffu, pl, j);
                uint2 raw = *reinterpret_cast<const uint2*>(xb + (size_t)p * Cn + lane * 4);
                __half2 h0 = *reinterpret_cast<__half2*>(&raw.x);
                __half2 h1 = *reinterpret_cast<__half2*>(&raw.y);
                float2 f0 = __half22float2(h0);
                float2 f1 = __half22float2(h1);
                ax += f0.x; ay += f0.y; az += f1.x; aw += f1.y;
            }
        }
        float4 acc = make_float4(ax, ay, az, aw);
        *reinterpret_cast<float4*>(
            &g_sums[((size_t)(s * Bn + b) * NSEGn + sg) * Cn + lane * 4]) = acc;
    }
}

// ---------------- K6: 1x1 conv over channels: tok = (sums/cnt) @ W^T + bias ------
__global__ void k_conv(const float* __restrict__ wgt,
                       const float* __restrict__ bias,
                       float* __restrict__ out)
{
    __shared__ float shm[32 * 128];
    __shared__ float shw[32 * 193];
    int t = threadIdx.x;
    int r0 = blockIdx.x * 32;

#pragma unroll
    for (int it = 0; it < 4; ++it) {
        int i = it * 256 + t;      // float4 index (1024 total)
        int row = i >> 5;
        int c4 = i & 31;
        *reinterpret_cast<float4*>(&shm[row * 128 + c4 * 4]) =
            *reinterpret_cast<const float4*>(&g_sums[(size_t)(r0 + row) * Cn + c4 * 4]);
    }

    int ty = t >> 5, tx = t & 31;
    float acc[4][6];
#pragma unroll
    for (int i = 0; i < 4; ++i)
#pragma unroll
        for (int j = 0; j < 6; ++j) acc[i][j] = 0.f;

    for (int cb = 0; cb < 4; ++cb) {
        __syncthreads();
#pragma unroll
        for (int it = 0; it < 24; ++it) {
            int i = it * 256 + t;  // 6144 elements
            int e = i >> 5;
            int c = i & 31;
            shw[c * 193 + e] = wgt[e * 128 + cb * 32 + c];
        }
        __syncthreads();
#pragma unroll
        for (int c = 0; c < 32; ++c) {
            float wv[6], mv[4];
#pragma unroll
            for (int j = 0; j < 6; ++j) wv[j] = shw[c * 193 + tx * 6 + j];
#pragma unroll
            for (int i = 0; i < 4; ++i) mv[i] = shm[(ty * 4 + i) * 128 + cb * 32 + c];
#pragma unroll
            for (int i = 0; i < 4; ++i)
#pragma unroll
                for (int j = 0; j < 6; ++j) acc[i][j] += mv[i] * wv[j];
        }
    }

    float bv[6];
#pragma unroll
    for (int j = 0; j < 6; ++j) bv[j] = __ldg(&bias[tx * 6 + j]);

#pragma unroll
    for (int i = 0; i < 4; ++i) {
        int r = r0 + ty * 4 + i;       // r = ((s*B + b)*1024 + n)
        int s  = r >> 13;
        int bb = (r >> 10) & 7;
        int n  = r & 1023;
        int cnt = g_cnt[(bb * SCALESn + s) * NSEGn + n];
        float inv = 1.0f / fmaxf((float)cnt, 1.0f);
        float* o = out + (size_t)s * TOK_SIZE
                       + (size_t)bb * TOKROWS * EMBEDn
                       + (size_t)(n + 1) * EMBEDn + tx * 6;
#pragma unroll
        for (int j = 0; j < 6; ++j) o[j] = acc[i][j] * inv + bv[j];
    }
}

// ---------------- K7: cls-token row (n = 0), identical for all (s,b) ----------
__global__ void k_cls(const float* __restrict__ wgt,
                      const float* __restrict__ bias,
                      const float* __restrict__ ct,
                      const float* __restrict__ cp,
                      float* __restrict__ out)
{
    int e = threadIdx.x;
    if (e >= EMBEDn) return;
    float a = bias[e];
    for (int c = 0; c < Cn; ++c)
        a += wgt[e * 128 + c] * (ct[c] + cp[c]);
    for (int s = 0; s < SCALESn; ++s)
        for (int b = 0; b < Bn; ++b)
            out[(size_t)s * TOK_SIZE + (size_t)b * TOKROWS * EMBEDn + e] = a;
}

// ---------------- launch ----------------
extern "C" void kernel_launch(void* const* d_in, const int* in_sizes, int n_in,
                              void* d_out, int out_size)
{
    const float* x   = (const float*)d_in[0];
    const int*   seg = (const int*)d_in[1];
    const float* ct  = (const float*)d_in[2];
    const float* cp  = (const float*)d_in[3];
    const float* cw  = (const float*)d_in[4];
    const float* cb  = (const float*)d_in[5];
    float* out = (float*)d_out;

    k_zero<<<32, 1024>>>();
    k_transpose<<<dim3(HWn / 64, Bn), 256>>>(x);
    k_hist<<<256, 256>>>(seg);
    k_scan<<<Bn * SCALESn, 1024>>>();
    k_scatter<<<256, 256>>>(seg, out + SEG_OUT_OFF);
    // one launch per image: xt[b] (64MB fp16) stays L2-resident across 4 scales
    for (int b = 0; b < Bn; ++b)
        k_reduce<<<256, 256>>>(b);
    k_conv<<<(SCALESn * Bn * NSEGn) / 32, 256>>>(cw, cb, out);
    k_cls<<<1, 192>>>(cw, cb, ct, cp, out);
}

// round 8
// speedup vs baseline: 1.5042x; 1.5042x over previous
#include <cuda_runtime.h>
#include <cuda_fp16.h>
#include <cstdint>

// Problem constants
#define Bn      8
#define Cn      128
#define HWn     262144          // 512*512
#define SCALESn 4
#define NSEGn   1024
#define EMBEDn  192
#define TOKROWS 1025
#define TOK_SIZE   (Bn*TOKROWS*EMBEDn)       // 1,574,400 per scale
#define SEG_TOTAL  (Bn*SCALESn*HWn)          // 8,388,608
#define SEG_OUT_OFF ((size_t)SCALESn*TOK_SIZE) // 6,297,600

// ---------------- scratch (static device globals; no runtime alloc) ----------
__device__ __half g_xt[(size_t)Bn*HWn*Cn];     // 0.5 GB: x transposed [b][pixel][c], fp16
__device__ int    g_sorted[SEG_TOTAL];         // sorted pixel ids per (b,scale)
__device__ int    g_cnt[Bn*SCALESn*NSEGn];     // per-segment counts
__device__ int    g_off[Bn*SCALESn*NSEGn];     // exclusive offsets
__device__ int    g_cursor[Bn*SCALESn*NSEGn];  // scatter cursors
__device__ float  g_sums[(size_t)SCALESn*Bn*NSEGn*Cn]; // [s][b][n][c]

// ---------------- K0: zero counts ----------------
__global__ void k_zero()
{
    int i = blockIdx.x * 1024 + threadIdx.x;
    if (i < Bn*SCALESn*NSEGn) g_cnt[i] = 0;
}

// ---------------- K1: transpose x [b][c][p] -> g_xt [b][p][c] (fp32 -> fp16) --
__global__ void k_transpose(const float* __restrict__ x)
{
    __shared__ float sm[64 * 129];
    int b  = blockIdx.y;
    int p0 = blockIdx.x * 64;
    const float* xb = x + (size_t)b * Cn * HWn;
    int t = threadIdx.x;

#pragma unroll
    for (int it = 0; it < 32; ++it) {
        int i  = it * 256 + t;
        int c  = i >> 6;
        int px = i & 63;
        sm[px * 129 + c] = xb[(size_t)c * HWn + p0 + px];
    }
    __syncthreads();
#pragma unroll
    for (int it = 0; it < 4; ++it) {
        int i  = it * 256 + t;
        int px = i >> 4;          // 0..63
        int g  = i & 15;          // 16-byte group within 256B row
        const float* s = &sm[px * 129 + g * 8];
        __half2 h0 = __floats2half2_rn(s[0], s[1]);
        __half2 h1 = __floats2half2_rn(s[2], s[3]);
        __half2 h2 = __floats2half2_rn(s[4], s[5]);
        __half2 h3 = __floats2half2_rn(s[6], s[7]);
        uint4 v;
        v.x = *reinterpret_cast<uint32_t*>(&h0);
        v.y = *reinterpret_cast<uint32_t*>(&h1);
        v.z = *reinterpret_cast<uint32_t*>(&h2);
        v.w = *reinterpret_cast<uint32_t*>(&h3);
        *reinterpret_cast<uint4*>(&g_xt[((size_t)b * HWn + p0 + px) * Cn + g * 8]) = v;
    }
}

// ---------------- K2: histogram (privatized in shared) ----------------
__global__ void k_hist(const int* __restrict__ seg)
{
    __shared__ int h[NSEGn];
    int bs = blockIdx.x >> 3;
    int chunk = blockIdx.x & 7;
    int t = threadIdx.x;
    for (int i = t; i < NSEGn; i += 256) h[i] = 0;
    __syncthreads();
    const int4* s4 = reinterpret_cast<const int4*>(seg + (size_t)bs * HWn + (size_t)chunk * 32768);
#pragma unroll 4
    for (int it = 0; it < 32; ++it) {
        int4 v = s4[it * 256 + t];
        atomicAdd(&h[v.x], 1);
        atomicAdd(&h[v.y], 1);
        atomicAdd(&h[v.z], 1);
        atomicAdd(&h[v.w], 1);
    }
    __syncthreads();
    for (int i = t; i < NSEGn; i += 256) atomicAdd(&g_cnt[bs * NSEGn + i], h[i]);
}

// ---------------- K3: exclusive scan of 1024 counts per (b,scale) ----------------
__global__ void k_scan()
{
    int bs = blockIdx.x;
    int t = threadIdx.x;
    int lane = t & 31, wid = t >> 5;
    int v = g_cnt[bs * NSEGn + t];
    int x = v;
#pragma unroll
    for (int d = 1; d < 32; d <<= 1) {
        int y = __shfl_up_sync(0xffffffffu, x, d);
        if (lane >= d) x += y;
    }
    __shared__ int ws[32];
    if (lane == 31) ws[wid] = x;
    __syncthreads();
    if (wid == 0) {
        int s = ws[lane];
#pragma unroll
        for (int d = 1; d < 32; d <<= 1) {
            int y = __shfl_up_sync(0xffffffffu, s, d);
            if (lane >= d) s += y;
        }
        ws[lane] = s;
    }
    __syncthreads();
    int excl = x - v + (wid ? ws[wid - 1] : 0);
    g_off[bs * NSEGn + t]    = excl;
    g_cursor[bs * NSEGn + t] = excl;
}

// ---------------- K4: scatter pixel ids into per-segment lists + seg cast-out ---
__global__ void k_scatter(const int* __restrict__ seg, float* __restrict__ segout)
{
    int bs = blockIdx.x >> 3;
    int chunk = blockIdx.x & 7;
    int t = threadIdx.x;
    const int4* s4 = reinterpret_cast<const int4*>(seg + (size_t)bs * HWn + (size_t)chunk * 32768);
    float4* o4 = reinterpret_cast<float4*>(segout + (size_t)bs * HWn + (size_t)chunk * 32768);
    int* cur = &g_cursor[bs * NSEGn];
    int* dst = &g_sorted[(size_t)bs * HWn];
#pragma unroll 2
    for (int it = 0; it < 32; ++it) {
        int i4 = it * 256 + t;
        int4 v = s4[i4];
        int px = chunk * 32768 + i4 * 4;
        int p;
        p = atomicAdd(cur + v.x, 1); dst[p] = px + 0;
        p = atomicAdd(cur + v.y, 1); dst[p] = px + 1;
        p = atomicAdd(cur + v.z, 1); dst[p] = px + 2;
        p = atomicAdd(cur + v.w, 1); dst[p] = px + 3;
        o4[i4] = make_float4((float)v.x, (float)v.y, (float)v.z, (float)v.w);
    }
}

// ---------------- K5: segment-sum via sorted gather (no atomics, fp16 rows) ------
// SINGLE launch, grid 512 x 256 (4096 warps, all wave-1 resident).
// One warp per (scale, seg); warps loop over the 8 images internally so each
// image's xt (64MB fp16) is L2-shared across its 4 concurrently-read scales.
// Inner loop issues 8 independent LDG.64 row loads before converting ->
// guaranteed MLP=8 per warp (~57KB in flight per SM > latency-BW product).
__global__ void k_reduce()
{
    int W = blockIdx.x * 8 + (threadIdx.x >> 5);   // 0..4095
    int lane = threadIdx.x & 31;
    int s  = W >> 10;
    int sg = W & 1023;

    for (int b = 0; b < Bn; ++b) {
        int bs = b * SCALESn + s;
        int off = g_off[bs * NSEGn + sg];
        int cnt = g_cnt[bs * NSEGn + sg];
        const int* list = g_sorted + (size_t)bs * HWn + off;
        const __half* xb = g_xt + (size_t)b * HWn * Cn;

        float ax = 0.f, ay = 0.f, az = 0.f, aw = 0.f;
        int i0 = 0;
        for (; i0 + 32 <= cnt; i0 += 32) {
            int pl = list[i0 + lane];
#pragma unroll
            for (int jj = 0; jj < 4; ++jj) {
                uint2 r[8];
#pragma unroll
                for (int j = 0; j < 8; ++j) {
                    int p = __shfl_sync(0xffffffffu, pl, jj * 8 + j);
                    r[j] = *reinterpret_cast<const uint2*>(xb + (size_t)p * Cn + lane * 4);
                }
#pragma unroll
                for (int j = 0; j < 8; ++j) {
                    __half2 h0 = *reinterpret_cast<__half2*>(&r[j].x);
                    __half2 h1 = *reinterpret_cast<__half2*>(&r[j].y);
                    float2 f0 = __half22float2(h0);
                    float2 f1 = __half22float2(h1);
                    ax += f0.x; ay += f0.y; az += f1.x; aw += f1.y;
                }
            }
        }
        if (i0 < cnt) {
            int idx = i0 + lane;
            int pl = (idx < cnt) ? list[idx] : 0;
            int m = cnt - i0;
            for (int j = 0; j < m; ++j) {
                int p = __shfl_sync(0xffffffffu, pl, j);
                uint2 rr = *reinterpret_cast<const uint2*>(xb + (size_t)p * Cn + lane * 4);
                __half2 h0 = *reinterpret_cast<__half2*>(&rr.x);
                __half2 h1 = *reinterpret_cast<__half2*>(&rr.y);
                float2 f0 = __half22float2(h0);
                float2 f1 = __half22float2(h1);
                ax += f0.x; ay += f0.y; az += f1.x; aw += f1.y;
            }
        }
        float4 acc = make_float4(ax, ay, az, aw);
        *reinterpret_cast<float4*>(
            &g_sums[((size_t)(s * Bn + b) * NSEGn + sg) * Cn + lane * 4]) = acc;
    }
}

// ---------------- K6: 1x1 conv over channels: tok = (sums/cnt) @ W^T + bias ------
__global__ void k_conv(const float* __restrict__ wgt,
                       const float* __restrict__ bias,
                       float* __restrict__ out)
{
    __shared__ float shm[32 * 128];
    __shared__ float shw[32 * 193];
    int t = threadIdx.x;
    int r0 = blockIdx.x * 32;

#pragma unroll
    for (int it = 0; it < 4; ++it) {
        int i = it * 256 + t;      // float4 index (1024 total)
        int row = i >> 5;
        int c4 = i & 31;
        *reinterpret_cast<float4*>(&shm[row * 128 + c4 * 4]) =
            *reinterpret_cast<const float4*>(&g_sums[(size_t)(r0 + row) * Cn + c4 * 4]);
    }

    int ty = t >> 5, tx = t & 31;
    float acc[4][6];
#pragma unroll
    for (int i = 0; i < 4; ++i)
#pragma unroll
        for (int j = 0; j < 6; ++j) acc[i][j] = 0.f;

    for (int cb = 0; cb < 4; ++cb) {
        __syncthreads();
#pragma unroll
        for (int it = 0; it < 24; ++it) {
            int i = it * 256 + t;  // 6144 elements
            int e = i >> 5;
            int c = i & 31;
            shw[c * 193 + e] = wgt[e * 128 + cb * 32 + c];
        }
        __syncthreads();
#pragma unroll
        for (int c = 0; c < 32; ++c) {
            float wv[6], mv[4];
#pragma unroll
            for (int j = 0; j < 6; ++j) wv[j] = shw[c * 193 + tx * 6 + j];
#pragma unroll
            for (int i = 0; i < 4; ++i) mv[i] = shm[(ty * 4 + i) * 128 + cb * 32 + c];
#pragma unroll
            for (int i = 0; i < 4; ++i)
#pragma unroll
                for (int j = 0; j < 6; ++j) acc[i][j] += mv[i] * wv[j];
        }
    }

    float bv[6];
#pragma unroll
    for (int j = 0; j < 6; ++j) bv[j] = __ldg(&bias[tx * 6 + j]);

#pragma unroll
    for (int i = 0; i < 4; ++i) {
        int r = r0 + ty * 4 + i;       // r = ((s*B + b)*1024 + n)
        int s  = r >> 13;
        int bb = (r >> 10) & 7;
        int n  = r & 1023;
        int cnt = g_cnt[(bb * SCALESn + s) * NSEGn + n];
        float inv = 1.0f / fmaxf((float)cnt, 1.0f);
        float* o = out + (size_t)s * TOK_SIZE
                       + (size_t)bb * TOKROWS * EMBEDn
                       + (size_t)(n + 1) * EMBEDn + tx * 6;
#pragma unroll
        for (int j = 0; j < 6; ++j) o[j] = acc[i][j] * inv + bv[j];
    }
}

// ---------------- K7: cls-token row (n = 0), identical for all (s,b) ----------
__global__ void k_cls(const float* __restrict__ wgt,
                      const float* __restrict__ bias,
                      const float* __restrict__ ct,
                      const float* __restrict__ cp,
                      float* __restrict__ out)
{
    int e = threadIdx.x;
    if (e >= EMBEDn) return;
    float a = bias[e];
    for (int c = 0; c < Cn; ++c)
        a += wgt[e * 128 + c] * (ct[c] + cp[c]);
    for (int s = 0; s < SCALESn; ++s)
        for (int b = 0; b < Bn; ++b)
            out[(size_t)s * TOK_SIZE + (size_t)b * TOKROWS * EMBEDn + e] = a;
}

// ---------------- launch ----------------
extern "C" void kernel_launch(void* const* d_in, const int* in_sizes, int n_in,
                              void* d_out, int out_size)
{
    const float* x   = (const float*)d_in[0];
    const int*   seg = (const int*)d_in[1];
    const float* ct  = (const float*)d_in[2];
    const float* cp  = (const float*)d_in[3];
    const float* cw  = (const float*)d_in[4];
    const float* cb  = (const float*)d_in[5];
    float* out = (float*)d_out;

    k_zero<<<32, 1024>>>();
    k_transpose<<<dim3(HWn / 64, Bn), 256>>>(x);
    k_hist<<<256, 256>>>(seg);
    k_scan<<<Bn * SCALESn, 1024>>>();
    k_scatter<<<256, 256>>>(seg, out + SEG_OUT_OFF);
    k_reduce<<<512, 256>>>();
    k_conv<<<(SCALESn * Bn * NSEGn) / 32, 256>>>(cw, cb, out);
    k_cls<<<1, 192>>>(cw, cb, ct, cp, out);
}

// round 9
// speedup vs baseline: 1.6669x; 1.1082x over previous
#include <cuda_runtime.h>
#include <cuda_fp16.h>
#include <cstdint>

// Problem constants
#define Bn      8
#define Cn      128
#define HWn     262144          // 512*512
#define SCALESn 4
#define NSEGn   1024
#define EMBEDn  192
#define TOKROWS 1025
#define TOK_SIZE   (Bn*TOKROWS*EMBEDn)       // 1,574,400 per scale
#define SEG_TOTAL  (Bn*SCALESn*HWn)          // 8,388,608
#define SEG_OUT_OFF ((size_t)SCALESn*TOK_SIZE) // 6,297,600

// ---------------- scratch (static device globals; no runtime alloc) ----------
__device__ __half g_xt[(size_t)Bn*HWn*Cn];     // 0.5 GB: x transposed [b][pixel][c], fp16
__device__ int    g_sorted[SEG_TOTAL];         // sorted pixel ids per (b,scale)
__device__ int    g_cnt[Bn*SCALESn*NSEGn];     // per-segment counts
__device__ int    g_off[Bn*SCALESn*NSEGn];     // exclusive offsets
__device__ int    g_cursor[Bn*SCALESn*NSEGn];  // scatter cursors
__device__ float  g_sums[(size_t)SCALESn*Bn*NSEGn*Cn]; // [s][b][n][c]

// ---------------- K0: zero counts ----------------
__global__ void k_zero()
{
    int i = blockIdx.x * 1024 + threadIdx.x;
    if (i < Bn*SCALESn*NSEGn) g_cnt[i] = 0;
}

// ---------------- K1: transpose x [b][c][p] -> g_xt [b][p][c] (fp32 -> fp16) --
__global__ void k_transpose(const float* __restrict__ x)
{
    __shared__ float sm[64 * 129];
    int b  = blockIdx.y;
    int p0 = blockIdx.x * 64;
    const float* xb = x + (size_t)b * Cn * HWn;
    int t = threadIdx.x;

#pragma unroll
    for (int it = 0; it < 32; ++it) {
        int i  = it * 256 + t;
        int c  = i >> 6;
        int px = i & 63;
        sm[px * 129 + c] = xb[(size_t)c * HWn + p0 + px];
    }
    __syncthreads();
#pragma unroll
    for (int it = 0; it < 4; ++it) {
        int i  = it * 256 + t;
        int px = i >> 4;          // 0..63
        int g  = i & 15;          // 16-byte group within 256B row
        const float* s = &sm[px * 129 + g * 8];
        __half2 h0 = __floats2half2_rn(s[0], s[1]);
        __half2 h1 = __floats2half2_rn(s[2], s[3]);
        __half2 h2 = __floats2half2_rn(s[4], s[5]);
        __half2 h3 = __floats2half2_rn(s[6], s[7]);
        uint4 v;
        v.x = *reinterpret_cast<uint32_t*>(&h0);
        v.y = *reinterpret_cast<uint32_t*>(&h1);
        v.z = *reinterpret_cast<uint32_t*>(&h2);
        v.w = *reinterpret_cast<uint32_t*>(&h3);
        *reinterpret_cast<uint4*>(&g_xt[((size_t)b * HWn + p0 + px) * Cn + g * 8]) = v;
    }
}

// ---------------- K2: histogram (privatized in shared) ----------------
__global__ void k_hist(const int* __restrict__ seg)
{
    __shared__ int h[NSEGn];
    int bs = blockIdx.x >> 3;
    int chunk = blockIdx.x & 7;
    int t = threadIdx.x;
    for (int i = t; i < NSEGn; i += 256) h[i] = 0;
    __syncthreads();
    const int4* s4 = reinterpret_cast<const int4*>(seg + (size_t)bs * HWn + (size_t)chunk * 32768);
#pragma unroll 4
    for (int it = 0; it < 32; ++it) {
        int4 v = s4[it * 256 + t];
        atomicAdd(&h[v.x], 1);
        atomicAdd(&h[v.y], 1);
        atomicAdd(&h[v.z], 1);
        atomicAdd(&h[v.w], 1);
    }
    __syncthreads();
    for (int i = t; i < NSEGn; i += 256) atomicAdd(&g_cnt[bs * NSEGn + i], h[i]);
}

// ---------------- K3: exclusive scan of 1024 counts per (b,scale) ----------------
__global__ void k_scan()
{
    int bs = blockIdx.x;
    int t = threadIdx.x;
    int lane = t & 31, wid = t >> 5;
    int v = g_cnt[bs * NSEGn + t];
    int x = v;
#pragma unroll
    for (int d = 1; d < 32; d <<= 1) {
        int y = __shfl_up_sync(0xffffffffu, x, d);
        if (lane >= d) x += y;
    }
    __shared__ int ws[32];
    if (lane == 31) ws[wid] = x;
    __syncthreads();
    if (wid == 0) {
        int s = ws[lane];
#pragma unroll
        for (int d = 1; d < 32; d <<= 1) {
            int y = __shfl_up_sync(0xffffffffu, s, d);
            if (lane >= d) s += y;
        }
        ws[lane] = s;
    }
    __syncthreads();
    int excl = x - v + (wid ? ws[wid - 1] : 0);
    g_off[bs * NSEGn + t]    = excl;
    g_cursor[bs * NSEGn + t] = excl;
}

// ---------------- K4: scatter pixel ids into per-segment lists + seg cast-out ---
__global__ void k_scatter(const int* __restrict__ seg, float* __restrict__ segout)
{
    int bs = blockIdx.x >> 3;
    int chunk = blockIdx.x & 7;
    int t = threadIdx.x;
    const int4* s4 = reinterpret_cast<const int4*>(seg + (size_t)bs * HWn + (size_t)chunk * 32768);
    float4* o4 = reinterpret_cast<float4*>(segout + (size_t)bs * HWn + (size_t)chunk * 32768);
    int* cur = &g_cursor[bs * NSEGn];
    int* dst = &g_sorted[(size_t)bs * HWn];
#pragma unroll 2
    for (int it = 0; it < 32; ++it) {
        int i4 = it * 256 + t;
        int4 v = s4[i4];
        int px = chunk * 32768 + i4 * 4;
        int p;
        p = atomicAdd(cur + v.x, 1); dst[p] = px + 0;
        p = atomicAdd(cur + v.y, 1); dst[p] = px + 1;
        p = atomicAdd(cur + v.z, 1); dst[p] = px + 2;
        p = atomicAdd(cur + v.w, 1); dst[p] = px + 3;
        o4[i4] = make_float4((float)v.x, (float)v.y, (float)v.z, (float)v.w);
    }
}

// ---------------- K5: segment-sum via sorted gather (no atomics, fp16 rows) ------
// SINGLE launch, grid 512 x 256 (4096 warps, all wave-1 resident).
// One warp per (scale, seg); warps loop over the 8 images internally so each
// image's xt (64MB fp16) is L2-shared across its 4 concurrently-read scales.
// NEW: 2 pixel rows per warp-instruction — lanes 0-15 cover the 128 channels
// (8 ch = one uint4 each) of the even pixel, lanes 16-31 of the odd pixel.
// One SHFL + one LDG.128 moves 512B; batches of 8 loads keep MLP=8.
__global__ void k_reduce()
{
    int W = blockIdx.x * 8 + (threadIdx.x >> 5);   // 0..4095
    int lane = threadIdx.x & 31;
    int half = lane >> 4;        // 0: even pixel, 1: odd pixel
    int li   = lane & 15;        // channel group: c = li*8 .. li*8+7
    int s  = W >> 10;
    int sg = W & 1023;

    for (int b = 0; b < Bn; ++b) {
        int bs = b * SCALESn + s;
        int off = g_off[bs * NSEGn + sg];
        int cnt = g_cnt[bs * NSEGn + sg];
        const int* list = g_sorted + (size_t)bs * HWn + off;
        const __half* xb = g_xt + (size_t)b * HWn * Cn;

        float acc[8];
#pragma unroll
        for (int k = 0; k < 8; ++k) acc[k] = 0.f;

        int i0 = 0;
        for (; i0 + 32 <= cnt; i0 += 32) {
            int pl = list[i0 + lane];
#pragma unroll
            for (int jj = 0; jj < 2; ++jj) {
                uint4 r[8];
#pragma unroll
                for (int j = 0; j < 8; ++j) {
                    int p = __shfl_sync(0xffffffffu, pl, jj * 16 + j * 2 + half);
                    r[j] = *reinterpret_cast<const uint4*>(xb + (size_t)p * Cn + li * 8);
                }
#pragma unroll
                for (int j = 0; j < 8; ++j) {
                    float2 f0 = __half22float2(*reinterpret_cast<__half2*>(&r[j].x));
                    float2 f1 = __half22float2(*reinterpret_cast<__half2*>(&r[j].y));
                    float2 f2 = __half22float2(*reinterpret_cast<__half2*>(&r[j].z));
                    float2 f3 = __half22float2(*reinterpret_cast<__half2*>(&r[j].w));
                    acc[0] += f0.x; acc[1] += f0.y;
                    acc[2] += f1.x; acc[3] += f1.y;
                    acc[4] += f2.x; acc[5] += f2.y;
                    acc[6] += f3.x; acc[7] += f3.y;
                }
            }
        }
        if (i0 < cnt) {
            int m = cnt - i0;
            int idx = i0 + lane;
            int pl = (idx < cnt) ? list[idx] : 0;
            int steps = (m + 1) >> 1;
            for (int jj = 0; jj < steps; ++jj) {
                int pi = jj * 2 + half;
                int p = __shfl_sync(0xffffffffu, pl, pi < 32 ? pi : 0);
                if (pi < m) {
                    uint4 r = *reinterpret_cast<const uint4*>(xb + (size_t)p * Cn + li * 8);
                    float2 f0 = __half22float2(*reinterpret_cast<__half2*>(&r.x));
                    float2 f1 = __half22float2(*reinterpret_cast<__half2*>(&r.y));
                    float2 f2 = __half22float2(*reinterpret_cast<__half2*>(&r.z));
                    float2 f3 = __half22float2(*reinterpret_cast<__half2*>(&r.w));
                    acc[0] += f0.x; acc[1] += f0.y;
                    acc[2] += f1.x; acc[3] += f1.y;
                    acc[4] += f2.x; acc[5] += f2.y;
                    acc[6] += f3.x; acc[7] += f3.y;
                }
            }
        }
        // combine even-pixel (lanes 0-15) and odd-pixel (lanes 16-31) partials
#pragma unroll
        for (int k = 0; k < 8; ++k)
            acc[k] += __shfl_xor_sync(0xffffffffu, acc[k], 16);
        if (half == 0) {
            float* o = &g_sums[((size_t)(s * Bn + b) * NSEGn + sg) * Cn + li * 8];
            *reinterpret_cast<float4*>(o)     = make_float4(acc[0], acc[1], acc[2], acc[3]);
            *reinterpret_cast<float4*>(o + 4) = make_float4(acc[4], acc[5], acc[6], acc[7]);
        }
    }
}

// ---------------- K6: 1x1 conv over channels: tok = (sums/cnt) @ W^T + bias ------
__global__ void k_conv(const float* __restrict__ wgt,
                       const float* __restrict__ bias,
                       float* __restrict__ out)
{
    __shared__ float shm[32 * 128];
    __shared__ float shw[32 * 193];
    int t = threadIdx.x;
    int r0 = blockIdx.x * 32;

#pragma unroll
    for (int it = 0; it < 4; ++it) {
        int i = it * 256 + t;      // float4 index (1024 total)
        int row = i >> 5;
        int c4 = i & 31;
        *reinterpret_cast<float4*>(&shm[row * 128 + c4 * 4]) =
            *reinterpret_cast<const float4*>(&g_sums[(size_t)(r0 + row) * Cn + c4 * 4]);
    }

    int ty = t >> 5, tx = t & 31;
    float acc[4][6];
#pragma unroll
    for (int i = 0; i < 4; ++i)
#pragma unroll
        for (int j = 0; j < 6; ++j) acc[i][j] = 0.f;

    for (int cb = 0; cb < 4; ++cb) {
        __syncthreads();
#pragma unroll
        for (int it = 0; it < 24; ++it) {
            int i = it * 256 + t;  // 6144 elements
            int e = i >> 5;
            int c = i & 31;
            shw[c * 193 + e] = wgt[e * 128 + cb * 32 + c];
        }
        __syncthreads();
#pragma unroll
        for (int c = 0; c < 32; ++c) {
            float wv[6], mv[4];
#pragma unroll
            for (int j = 0; j < 6; ++j) wv[j] = shw[c * 193 + tx * 6 + j];
#pragma unroll
            for (int i = 0; i < 4; ++i) mv[i] = shm[(ty * 4 + i) * 128 + cb * 32 + c];
#pragma unroll
            for (int i = 0; i < 4; ++i)
#pragma unroll
                for (int j = 0; j < 6; ++j) acc[i][j] += mv[i] * wv[j];
        }
    }

    float bv[6];
#pragma unroll
    for (int j = 0; j < 6; ++j) bv[j] = __ldg(&bias[tx * 6 + j]);

#pragma unroll
    for (int i = 0; i < 4; ++i) {
        int r = r0 + ty * 4 + i;       // r = ((s*B + b)*1024 + n)
        int s  = r >> 13;
        int bb = (r >> 10) & 7;
        int n  = r & 1023;
        int cnt = g_cnt[(bb * SCALESn + s) * NSEGn + n];
        float inv = 1.0f / fmaxf((float)cnt, 1.0f);
        float* o = out + (size_t)s * TOK_SIZE
                       + (size_t)bb * TOKROWS * EMBEDn
                       + (size_t)(n + 1) * EMBEDn + tx * 6;
#pragma unroll
        for (int j = 0; j < 6; ++j) o[j] = acc[i][j] * inv + bv[j];
    }
}

// ---------------- K7: cls-token row (n = 0), identical for all (s,b) ----------
__global__ void k_cls(const float* __restrict__ wgt,
                      const float* __restrict__ bias,
                      const float* __restrict__ ct,
                      const float* __restrict__ cp,
                      float* __restrict__ out)
{
    int e = threadIdx.x;
    if (e >= EMBEDn) return;
    float a = bias[e];
    for (int c = 0; c < Cn; ++c)
        a += wgt[e * 128 + c] * (ct[c] + cp[c]);
    for (int s = 0; s < SCALESn; ++s)
        for (int b = 0; b < Bn; ++b)
            out[(size_t)s * TOK_SIZE + (size_t)b * TOKROWS * EMBEDn + e] = a;
}

// ---------------- launch ----------------
extern "C" void kernel_launch(void* const* d_in, const int* in_sizes, int n_in,
                              void* d_out, int out_size)
{
    const float* x   = (const float*)d_in[0];
    const int*   seg = (const int*)d_in[1];
    const float* ct  = (const float*)d_in[2];
    const float* cp  = (const float*)d_in[3];
    const float* cw  = (const float*)d_in[4];
    const float* cb  = (const float*)d_in[5];
    float* out = (float*)d_out;

    k_zero<<<32, 1024>>>();
    k_transpose<<<dim3(HWn / 64, Bn), 256>>>(x);
    k_hist<<<256, 256>>>(seg);
    k_scan<<<Bn * SCALESn, 1024>>>();
    k_scatter<<<256, 256>>>(seg, out + SEG_OUT_OFF);
    k_reduce<<<512, 256>>>();
    k_conv<<<(SCALESn * Bn * NSEGn) / 32, 256>>>(cw, cb, out);
    k_cls<<<1, 192>>>(cw, cb, ct, cp, out);
}